// round 9
// baseline (speedup 1.0000x reference)
#include <cuda_runtime.h>
#include <math.h>

typedef unsigned long long u64;

#define BATCH 64
#define H 224
#define W 224
#define NPAIR 192
#define ACC_STRIDE 132
#define RW 228                // smem row width: 224 + right guard, mult of 4

// Device scratch. finalize self-zeroes g_acc after reading (replay-safe).
__device__ float g_feat[BATCH * 75];
__device__ int   g_acc[5 * NPAIR * ACC_STRIDE];   // seg: 0:k3 1:k5 2:k7 3:k9 4:k11

// ---------------- K=11 column masks (stride 11, 2x u64) --------------------
constexpr u64 colmask_lo(int c) {
    u64 m = 0;
    for (int r = 0; r < 11; r++) { int p = r * 11 + c; if (p < 64) m |= 1ull << p; }
    return m;
}
constexpr u64 colmask_hi(int c) {
    u64 m = 0;
    for (int r = 0; r < 11; r++) { int p = r * 11 + c; if (p >= 64) m |= 1ull << (p - 64); }
    return m;
}
constexpr u64 NOTC0_LO  = ~colmask_lo(0);
constexpr u64 NOTC0_HI  = ~colmask_hi(0);
constexpr u64 NOTC10_LO = ~colmask_lo(10);
constexpr u64 NOTC10_HI = ~colmask_hi(10);

template <int K>
__device__ __forceinline__ void expand128(u64 clo, u64 chi, u64& glo, u64& ghi) {
    u64 l1lo = clo << 1;
    u64 l1hi = (chi << 1) | (clo >> 63);
    u64 r1lo = (clo >> 1) | (chi << 63);
    u64 r1hi = chi >> 1;
    if (K == 11) {
        l1lo &= NOTC0_LO;  l1hi &= NOTC0_HI;
        r1lo &= NOTC10_LO; r1hi &= NOTC10_HI;
    }
    u64 uplo = clo << 11;
    u64 uphi = (chi << 11) | (clo >> 53);
    u64 dnlo = (clo >> 11) | (chi << 53);
    u64 dnhi = chi >> 11;
    glo = l1lo | r1lo | uplo | dnlo;
    ghi = l1hi | r1hi | uphi | dnhi;
}

// ===========================================================================
// NARROW kernel: k = 3,5,7. 256-thread blocks, 3-channel smem bands.
// K=3 uses a 512-entry LUT for connected components.
// ===========================================================================
#define NB7 (64 * 16)
#define NB5 (64 * 15)
#define NB3 (64 * 15)
#define NARROW_BLOCKS (NB7 + NB5 + NB3)       // 2944
#define NARROW_DYN (3 * 15 * RW * 4)          // 41040 bytes

__device__ __forceinline__ void build_lut3(int tid, unsigned short* lut) {
    for (int m = tid; m < 512; m += 256) {
        int nc = 0, best = 0, rem = m;
        while (rem) {
            int cur = rem & (-rem);
            while (true) {
                int g = cur | ((cur << 1) & 0x1B6) | ((cur >> 1) & 0x0DB)
                            | (cur << 3) | (cur >> 3);
                g &= rem;
                if (g == cur) break;
                cur = g;
            }
            nc++;
            int a = __popc(cur);
            if (a > best) best = a;
            rem ^= cur;
        }
        lut[m] = (unsigned short)(nc | (best << 8));
    }
}

template <int K, int BR, int SEG>
__device__ __forceinline__ void narrow_band(const float4* __restrict__ in4, int rel,
                                            float* sm, int* shh, int* shs,
                                            unsigned short* lut) {
    constexpr int ROWS  = (H + K - 1) / K;
    constexpr int COLS  = (W + K - 1) / K;
    constexpr int KK    = K * K;
    constexpr int BANDS = ROWS / BR;           // exact for 3,5,7
    constexpr int NR    = BR * K;
    constexpr int plane = NR * RW;

    const int b    = rel / BANDS;
    const int band = rel % BANDS;
    const int tid  = threadIdx.x;
    const int rbase = band * NR;

    if (K == 3) build_lut3(tid, lut);

    for (int i = tid; i < 3 * 128; i += 256) shh[i] = 0;
    if (tid < 9) shs[tid] = 0;
    {
        float4 z = make_float4(0.f, 0.f, 0.f, 0.f);
        float4* sm4 = (float4*)sm;
        const int nz = 3 * NR * (RW / 4);
        for (int i = tid; i < nz; i += 256) sm4[i] = z;
    }
    __syncthreads();

    // coalesced NHWC load + deinterleave into 3 planes
    {
        const int r_hi  = (rbase + NR > H) ? H : (rbase + NR);
        const int nload = (r_hi - rbase) * 56;
        const float4* src = in4 + b * 37632;
        for (int t = tid; t < nload; t += 256) {
            int s = t / 56, g = t - s * 56;
            int r = rbase + s;
            int gb = r * 168 + 3 * g;
            float4 f0 = src[gb], f1 = src[gb + 1], f2 = src[gb + 2];
            int sb = s * RW + 4 * g;
            *(float4*)(sm + sb)             = make_float4(f0.x, f0.w, f1.z, f2.y);
            *(float4*)(sm + plane + sb)     = make_float4(f0.y, f1.x, f1.w, f2.z);
            *(float4*)(sm + 2 * plane + sb) = make_float4(f0.z, f1.y, f2.x, f2.w);
        }
    }
    __syncthreads();

    constexpr int nbc = BR * COLS;
    constexpr int NP  = 3 * nbc;
    int cur_ch = 0, tnc = 0, tpc = 0, tma = 0;

    for (int pidx = tid; pidx < NP; pidx += 256) {
        int ch = pidx / nbc;
        int q  = pidx - ch * nbc;
        int il = q / COLS;
        int j  = q - il * COLS;

        if (ch != cur_ch) {
            if (tnc | tpc | tma) {
                atomicAdd(&shs[cur_ch * 3 + 0], tnc);
                atomicAdd(&shs[cur_ch * 3 + 1], tpc);
                atomicAdd(&shs[cur_ch * 3 + 2], tma);
            }
            tnc = tpc = tma = 0;
            cur_ch = ch;
        }

        const float* pl = sm + ch * plane + il * K * RW + j * K;
        const float center = pl[(K / 2) * RW + K / 2];

        int ones, nc, best;
        if (K == 3) {
            int m9 = 0;
            #pragma unroll
            for (int dy = 0; dy < 3; dy++)
                #pragma unroll
                for (int dx = 0; dx < 3; dx++) {
                    float v = pl[dy * RW + dx];
                    if (fabsf(v - center) <= 3.0f) m9 |= 1 << (3 * dy + dx);
                }
            ones = __popc(m9);
            unsigned val = lut[m9];
            nc = val & 0xFF;
            best = val >> 8;
            if (9 - ones > best) best = 9 - ones;
        } else {
            u64 mm = 0;
            #pragma unroll
            for (int dy = 0; dy < K; dy++) {
                unsigned m = 0;
                #pragma unroll
                for (int dx = 0; dx < K; dx++) {
                    float v = pl[dy * RW + dx];
                    if (fabsf(v - center) <= (float)K) m |= (1u << dx);
                }
                mm |= (u64)m << (dy * 8);
            }
            ones = __popcll(mm);
            best = KK - ones;
            u64 neigh = (mm << 1) | (mm >> 1) | (mm << 8) | (mm >> 8);
            u64 iso = mm & ~neigh;
            nc = __popcll(iso);
            u64 rem = mm ^ iso;
            while (rem) {
                u64 cur = rem & (0ull - rem);
                while (true) {
                    u64 g1 = (cur | (cur << 1) | (cur >> 1) | (cur << 8) | (cur >> 8)) & rem;
                    u64 g2 = (g1 | (g1 << 1) | (g1 >> 1) | (g1 << 8) | (g1 >> 8)) & rem;
                    if (g2 == cur) break;
                    cur = g2;
                }
                int a = __popcll(cur);
                if (a > best) best = a;
                rem ^= cur;
                nc++;
            }
        }

        {
            int key = ch * 128 + ones;
            unsigned act   = __activemask();
            unsigned peers = __match_any_sync(act, key);
            if ((tid & 31) == (__ffs(peers) - 1))
                atomicAdd(&shh[key], __popc(peers));
        }
        tnc += nc;
        tpc += ((float)ones / (float)KK >= 0.59275f) ? 1 : 0;
        tma += best;
    }
    if (tnc | tpc | tma) {
        atomicAdd(&shs[cur_ch * 3 + 0], tnc);
        atomicAdd(&shs[cur_ch * 3 + 1], tpc);
        atomicAdd(&shs[cur_ch * 3 + 2], tma);
    }
    __syncthreads();

    for (int i = tid; i < 3 * 131; i += 256) {
        int ch = i / 131, q = i - ch * 131;
        int v = (q < 128) ? shh[ch * 128 + q] : shs[ch * 3 + (q - 128)];
        if (v) atomicAdd(&g_acc[(SEG * NPAIR + b * 3 + ch) * ACC_STRIDE + q], v);
    }
}

__global__ __launch_bounds__(256, 5) void narrow_kernel(const float4* __restrict__ in4) {
    extern __shared__ float sm[];
    __shared__ int shh[3 * 128];
    __shared__ int shs[9];
    __shared__ unsigned short lut[512];
    const int blk = blockIdx.x;
    if (blk < NB7)            narrow_band<7, 2, 2>(in4, blk, sm, shh, shs, lut);
    else if (blk < NB7 + NB5) narrow_band<5, 3, 1>(in4, blk - NB7, sm, shh, shs, lut);
    else                      narrow_band<3, 5, 0>(in4, blk - NB7 - NB5, sm, shh, shs, lut);
}

// ===========================================================================
// WIDE kernel: k = 9,11. Patch-per-thread from NHWC global, flat grid.
// ===========================================================================
#define NW9  ((625 * NPAIR + 255) / 256)   // 469
#define NW11 ((441 * NPAIR + 255) / 256)   // 331

template <int K, int SEG>
__device__ __forceinline__ void wide_patch(const float* __restrict__ in, int gid) {
    constexpr int ROWS = (H + K - 1) / K;
    constexpr int COLS = (W + K - 1) / K;
    constexpr int P    = ROWS * COLS;
    constexpr int PADT = (ROWS * K - H) / 2;
    constexpr int PADL = (COLS * K - W) / 2;
    constexpr int KK   = K * K;
    constexpr bool HASNEG = (K == 11);

    if (gid >= P * NPAIR) return;
    const int pair = gid / P;
    const int pidx = gid - pair * P;
    const int b  = pair / 3;
    const int ch = pair % 3;
    const float* __restrict__ img = in + b * (H * W * 3) + ch;

    const int i  = pidx / COLS;
    const int j  = pidx - i * COLS;
    const int r0 = i * K - PADT;
    const int c0 = j * K - PADL;

    const float center = __ldg(img + ((r0 + K / 2) * W + (c0 + K / 2)) * 3);
    const bool interior = (!HASNEG || ((r0 >= 0) & (c0 >= 0))) &
                          (r0 + K <= H) & (c0 + K <= W);

    u64 mlo = 0, mhi = 0;
    if (interior) {
        const float* base = img + (r0 * W + c0) * 3;
        #pragma unroll
        for (int dy = 0; dy < K; dy++) {
            unsigned m = 0;
            #pragma unroll
            for (int dx = 0; dx < K; dx++) {
                float v = __ldg(base + (dy * W + dx) * 3);
                if (fabsf(v - center) <= (float)K) m |= (1u << dx);
            }
            int p = dy * 11;
            if (p < 64) {
                mlo |= (u64)m << p;
                if (p + K > 64) mhi |= (u64)m >> (64 - p);
            } else {
                mhi |= (u64)m << (p - 64);
            }
        }
    } else {
        #pragma unroll
        for (int dy = 0; dy < K; dy++) {
            const int r = r0 + dy;
            unsigned m = 0;
            #pragma unroll
            for (int dx = 0; dx < K; dx++) {
                const int c = c0 + dx;
                bool ok = HASNEG ? ((unsigned)r < (unsigned)H && (unsigned)c < (unsigned)W)
                                 : (r < H && c < W);
                float v = ok ? __ldg(img + (r * W + c) * 3) : 0.0f;
                if (fabsf(v - center) <= (float)K) m |= (1u << dx);
            }
            int p = dy * 11;
            if (p < 64) {
                mlo |= (u64)m << p;
                if (p + K > 64) mhi |= (u64)m >> (64 - p);
            } else {
                mhi |= (u64)m << (p - 64);
            }
        }
    }

    const int ones = __popcll(mlo) + __popcll(mhi);
    int best = KK - ones;
    u64 nlo, nhi;
    expand128<K>(mlo, mhi, nlo, nhi);
    u64 isolo = mlo & ~nlo, isohi = mhi & ~nhi;
    int nc = __popcll(isolo) + __popcll(isohi);
    u64 rlo = mlo ^ isolo, rhi = mhi ^ isohi;
    while (rlo | rhi) {
        u64 clo, chi;
        if (rlo) { clo = rlo & (0ull - rlo); chi = 0; }
        else     { clo = 0; chi = rhi & (0ull - rhi); }
        while (true) {
            u64 elo, ehi, g1lo, g1hi, g2lo, g2hi;
            expand128<K>(clo, chi, elo, ehi);
            g1lo = (clo | elo) & rlo;
            g1hi = (chi | ehi) & rhi;
            expand128<K>(g1lo, g1hi, elo, ehi);
            g2lo = (g1lo | elo) & rlo;
            g2hi = (g1hi | ehi) & rhi;
            if (g2lo == clo && g2hi == chi) break;
            clo = g2lo; chi = g2hi;
        }
        int a = __popcll(clo) + __popcll(chi);
        if (a > best) best = a;
        rlo ^= clo; rhi ^= chi;
        nc++;
    }

    const int pc = ((float)ones / (float)KK >= 0.59275f) ? 1 : 0;
    int* acc = g_acc + (SEG * NPAIR + pair) * ACC_STRIDE;

    unsigned act = __activemask();
    const int lane = threadIdx.x & 31;
    {
        int key = pair * 132 + ones;
        unsigned peers = __match_any_sync(act, key);
        if (lane == (__ffs(peers) - 1))
            atomicAdd(&acc[ones], __popc(peers));
    }
    unsigned same = __match_any_sync(act, pair);
    if (same == act) {
        int snc = __reduce_add_sync(act, nc);
        int spc = __reduce_add_sync(act, pc);
        int sma = __reduce_add_sync(act, best);
        if (lane == (__ffs(act) - 1)) {
            atomicAdd(&acc[128], snc);
            atomicAdd(&acc[129], spc);
            atomicAdd(&acc[130], sma);
        }
    } else {
        atomicAdd(&acc[128], nc);
        atomicAdd(&acc[129], pc);
        atomicAdd(&acc[130], best);
    }
}

__global__ __launch_bounds__(256, 4) void wide_kernel(const float* __restrict__ in) {
    const int blk = blockIdx.x;
    if (blk < NW9) wide_patch<9, 3>(in, blk * 256 + threadIdx.x);
    else           wide_patch<11, 4>(in, (blk - NW9) * 256 + threadIdx.x);
}

// ===========================================================================
// Finalize: metrics -> g_feat, then self-zero g_acc
// ===========================================================================
__global__ void finalize_kernel() {
    int tid = blockIdx.x * blockDim.x + threadIdx.x;
    if (tid >= 5 * NPAIR) return;
    const int seg  = tid / NPAIR;
    const int pair = tid % NPAIR;
    const int b  = pair / 3;
    const int ch = pair % 3;

    const int K  = 3 + 2 * seg;
    const int KK = K * K;
    const int ROWS = (H + K - 1) / K;
    const int COLS = (W + K - 1) / K;
    const int P    = ROWS * COLS;

    int* acc = g_acc + (seg * NPAIR + pair) * ACC_STRIDE;
    const float fP = (float)P;
    float fd = 0.0f, m = 0.0f, m2 = 0.0f;
    for (int q = 0; q < KK; q++) {
        float p = (float)acc[q] / fP;
        float n = (float)(q + 1);
        fd += p / n;
        m  += p * n;
        m2 += p * p * n;
    }
    float lac = (m2 - m * m) / (m * m);
    int acn  = acc[128] / P;
    int acp  = acc[129] / P;
    int acma = acc[130] / P;

    const int o = ((b * 5) * 5 + seg) * 3 + ch;
    g_feat[o + 0 * 15] = (float)acn;
    g_feat[o + 1 * 15] = (float)acp;
    g_feat[o + 2 * 15] = (float)acma;
    g_feat[o + 3 * 15] = lac;
    g_feat[o + 4 * 15] = fd;

    for (int q = 0; q < 131; q++) acc[q] = 0;
}

// ===========================================================================
// Resize (unchanged from R8 best)
// ===========================================================================
#define RCHUNK 28
#define YBLKS (H / RCHUNK)
#define WC (W * 3)

__global__ __launch_bounds__(256) void resize_kernel(float* __restrict__ out) {
    __shared__ float feat[75];
    __shared__ __align__(16) float hrow[5 * WC];
    __shared__ float s_fy[RCHUNK];
    __shared__ int   s_y0[RCHUNK], s_y1[RCHUNK];

    const int b   = blockIdx.x / YBLKS;
    const int yc  = blockIdx.x % YBLKS;
    const int tid = threadIdx.x;

    if (tid < 75) feat[tid] = g_feat[b * 75 + tid];
    if (tid >= 96 && tid < 96 + RCHUNK) {
        int y = yc * RCHUNK + (tid - 96);
        float cy = ((float)y + 0.5f) * (5.0f / 224.0f) - 0.5f;
        float fl = floorf(cy);
        int y0 = (int)fl;
        float fy = cy - fl;
        int y0c = max(y0, 0), y1c = min(y0 + 1, 4);
        s_fy[tid - 96] = fy;
        s_y0[tid - 96] = y0c * WC;
        s_y1[tid - 96] = y1c * WC;
    }
    __syncthreads();

    for (int i = tid; i < 5 * WC; i += 256) {
        int r  = i / WC;
        int xc = i - r * WC;
        int x  = xc / 3;
        int ch = xc - x * 3;
        float cx = ((float)x + 0.5f) * (5.0f / 224.0f) - 0.5f;
        float fl = floorf(cx);
        int x0 = (int)fl;
        float fx = cx - fl;
        int x0c = max(x0, 0), x1c = min(x0 + 1, 4);
        float a  = feat[(r * 5 + x0c) * 3 + ch];
        float bb = feat[(r * 5 + x1c) * 3 + ch];
        hrow[i] = a + fx * (bb - a);
    }
    __syncthreads();

    float4* o4 = (float4*)(out + b * (H * WC) + yc * (RCHUNK * WC));
    const int N4 = RCHUNK * WC / 4;
    for (int i = tid; i < N4; i += 256) {
        int yl = i / (WC / 4);
        int x4 = i - yl * (WC / 4);
        const float4 a  = *(const float4*)&hrow[s_y0[yl] + 4 * x4];
        const float4 bb = *(const float4*)&hrow[s_y1[yl] + 4 * x4];
        const float fy = s_fy[yl];
        float4 v;
        v.x = a.x + fy * (bb.x - a.x);
        v.y = a.y + fy * (bb.y - a.y);
        v.z = a.z + fy * (bb.z - a.z);
        v.w = a.w + fy * (bb.w - a.w);
        o4[i] = v;
    }
}

// ---------------------------------------------------------------------------
extern "C" void kernel_launch(void* const* d_in, const int* in_sizes, int n_in,
                              void* d_out, int out_size) {
    const float* in = (const float*)d_in[0];
    float* out = (float*)d_out;

    cudaFuncSetAttribute(narrow_kernel,
                         cudaFuncAttributeMaxDynamicSharedMemorySize, NARROW_DYN);
    wide_kernel<<<NW9 + NW11, 256>>>(in);
    narrow_kernel<<<NARROW_BLOCKS, 256, NARROW_DYN>>>((const float4*)in);
    finalize_kernel<<<(5 * NPAIR + 127) / 128, 128>>>();
    resize_kernel<<<BATCH * YBLKS, 256>>>(out);
}

// round 10
// speedup vs baseline: 1.3757x; 1.3757x over previous
#include <cuda_runtime.h>
#include <math.h>

typedef unsigned long long u64;

#define BATCH 64
#define H 224
#define W 224
#define NPAIR 192            // BATCH*3
#define ACC_STRIDE 132       // 128 hist bins + nc/pc/ma + pad
#define ACC_INTS (5 * NPAIR * ACC_STRIDE)

// Segment order heavy-first: k = 11,9,7,5,3 ; 256-thread blocks
#define C11 2
#define C9  3
#define C7  4
#define C5  8
#define C3  22
#define O11 0
#define O9  (O11 + C11 * NPAIR)
#define O7  (O9  + C9  * NPAIR)
#define O5  (O7  + C7  * NPAIR)
#define O3  (O5  + C5  * NPAIR)
#define TOTAL_BLOCKS (O3 + C3 * NPAIR)   // 39*192 = 7488

// Device scratch (no allocation allowed)
__device__ float g_planes[3][BATCH * H * W];
__device__ float g_feat[BATCH * 75];
__device__ int   g_acc[ACC_INTS];
__device__ unsigned short g_lut3[512];   // k=3 mask -> {nc | maxarea<<8}

// Column masks for K=11 (stride 11, 128-bit mask in 2x u64)
constexpr u64 colmask_lo(int c) {
    u64 m = 0;
    for (int r = 0; r < 11; r++) { int p = r * 11 + c; if (p < 64) m |= 1ull << p; }
    return m;
}
constexpr u64 colmask_hi(int c) {
    u64 m = 0;
    for (int r = 0; r < 11; r++) { int p = r * 11 + c; if (p >= 64) m |= 1ull << (p - 64); }
    return m;
}
constexpr u64 NOTC0_LO  = ~colmask_lo(0);
constexpr u64 NOTC0_HI  = ~colmask_hi(0);
constexpr u64 NOTC10_LO = ~colmask_lo(10);
constexpr u64 NOTC10_HI = ~colmask_hi(10);

// ---------------------------------------------------------------------------
// Kernel 1: NHWC -> channel planes (float4) + zero accumulators + build k3 LUT
// ---------------------------------------------------------------------------
__global__ void transpose_kernel(const float4* __restrict__ in4) {
    int t = blockIdx.x * blockDim.x + threadIdx.x;
    if (t < ACC_INTS) g_acc[t] = 0;
    if (t < 512) {
        // 9-bit mask CC: nc and max component area (exact, 4-connected)
        int nc = 0, best = 0, rem = t;
        while (rem) {
            int cur = rem & (-rem);
            while (true) {
                int g = cur | ((cur << 1) & 0x1B6) | ((cur >> 1) & 0x0DB)
                            | (cur << 3) | (cur >> 3);
                g &= rem;
                if (g == cur) break;
                cur = g;
            }
            nc++;
            int a = __popc(cur);
            if (a > best) best = a;
            rem ^= cur;
        }
        g_lut3[t] = (unsigned short)(nc | (best << 8));
    }
    const int NT = BATCH * H * W / 4;   // 802816
    if (t >= NT) return;
    float4 f0 = in4[3 * t + 0];
    float4 f1 = in4[3 * t + 1];
    float4 f2 = in4[3 * t + 2];
    ((float4*)g_planes[0])[t] = make_float4(f0.x, f0.w, f1.z, f2.y);
    ((float4*)g_planes[1])[t] = make_float4(f0.y, f1.x, f1.w, f2.z);
    ((float4*)g_planes[2])[t] = make_float4(f0.z, f1.y, f2.x, f2.w);
}

// 128-bit neighbor expansion (stride 11)
template <int K>
__device__ __forceinline__ void expand128(u64 clo, u64 chi, u64& glo, u64& ghi) {
    u64 l1lo = clo << 1;
    u64 l1hi = (chi << 1) | (clo >> 63);
    u64 r1lo = (clo >> 1) | (chi << 63);
    u64 r1hi = chi >> 1;
    if (K == 11) {
        l1lo &= NOTC0_LO;  l1hi &= NOTC0_HI;
        r1lo &= NOTC10_LO; r1hi &= NOTC10_HI;
    }
    u64 uplo = clo << 11;
    u64 uphi = (chi << 11) | (clo >> 53);
    u64 dnlo = (clo >> 11) | (chi << 53);
    u64 dnhi = chi >> 11;
    glo = l1lo | r1lo | uplo | dnlo;
    ghi = l1hi | r1hi | uphi | dnhi;
}

// ---------------------------------------------------------------------------
// Patch body (templated on K); k=3 via LUT, else singleton-elim bitmask CC
// ---------------------------------------------------------------------------
template <int K, int CHUNKS, int SEG>
__device__ __forceinline__ void patch_body(int rel, int* sh) {
    constexpr int ROWS = (H + K - 1) / K;
    constexpr int COLS = (W + K - 1) / K;
    constexpr int P    = ROWS * COLS;
    constexpr int PADT = (ROWS * K - H) / 2;
    constexpr int PADL = (COLS * K - W) / 2;
    constexpr int KK   = K * K;
    constexpr int STRIDE = (K <= 7) ? 8 : 11;
    constexpr bool WIDE  = (K > 7);
    // integer percolation threshold: ones/KK >= 0.59275  <=>  ones >= PTH
    constexpr int PTH = (K == 3) ? 6 : (K == 5) ? 15 : (K == 7) ? 30
                       : (K == 9) ? 49 : 72;

    const int chunk = rel / NPAIR;
    const int pair  = rel % NPAIR;
    const int b  = pair / 3;
    const int ch = pair % 3;
    const float* __restrict__ plane = g_planes[ch] + b * (H * W);

    for (int i = threadIdx.x; i < ACC_STRIDE - 1; i += 256) sh[i] = 0;
    __syncthreads();

    int t_nc = 0, t_pc = 0, t_ma = 0;

    for (int pidx = chunk * 256 + threadIdx.x; pidx < P;
         pidx += CHUNKS * 256) {
        const int i  = pidx / COLS;
        const int j  = pidx % COLS;
        const int r0 = i * K - PADT;
        const int c0 = j * K - PADL;

        const float center = __ldg(plane + (r0 + K / 2) * W + (c0 + K / 2));
        const bool interior = (r0 >= 0) & (c0 >= 0) & (r0 + K <= H) & (c0 + K <= W);

        u64 mlo = 0, mhi = 0;
        if (interior) {
            const float* base = plane + r0 * W + c0;
            #pragma unroll
            for (int dy = 0; dy < K; dy++) {
                unsigned m = 0;
                #pragma unroll
                for (int dx = 0; dx < K; dx++) {
                    float v = __ldg(base + dy * W + dx);
                    if (fabsf(v - center) <= (float)K) m |= (1u << dx);
                }
                int p = dy * STRIDE;
                if (p < 64) {
                    mlo |= (u64)m << p;
                    if (p + K > 64) mhi |= (u64)m >> (64 - p);
                } else {
                    mhi |= (u64)m << (p - 64);
                }
            }
        } else {
            #pragma unroll
            for (int dy = 0; dy < K; dy++) {
                const int r = r0 + dy;
                unsigned m = 0;
                #pragma unroll
                for (int dx = 0; dx < K; dx++) {
                    const int c = c0 + dx;
                    float v = ((unsigned)r < (unsigned)H && (unsigned)c < (unsigned)W)
                                  ? __ldg(plane + r * W + c) : 0.0f;
                    if (fabsf(v - center) <= (float)K) m |= (1u << dx);
                }
                int p = dy * STRIDE;
                if (p < 64) {
                    mlo |= (u64)m << p;
                    if (p + K > 64) mhi |= (u64)m >> (64 - p);
                } else {
                    mhi |= (u64)m << (p - 64);
                }
            }
        }

        int ones, nc, best;

        if (K == 3) {
            // compact stride-8 mask into 9 bits, then LUT
            int m9 = (int)(mlo & 7u) | ((int)(mlo >> 8) & 7) << 3
                   | ((int)(mlo >> 16) & 7) << 6;
            ones = __popc(m9);
            unsigned val = __ldg(&g_lut3[m9]);
            nc = val & 0xFF;
            best = val >> 8;
            int bg = 9 - ones;
            if (bg > best) best = bg;
        } else if (!WIDE) {
            ones = __popcll(mlo);
            best = KK - ones;
            const u64 m = mlo;
            u64 neigh = (m << 1) | (m >> 1) | (m << 8) | (m >> 8);
            u64 iso = m & ~neigh;
            nc = __popcll(iso);
            u64 rem = m ^ iso;
            while (rem) {
                u64 cur = rem & (0ull - rem);
                while (true) {
                    u64 g1 = (cur | (cur << 1) | (cur >> 1) | (cur << 8) | (cur >> 8)) & rem;
                    u64 g2 = (g1 | (g1 << 1) | (g1 >> 1) | (g1 << 8) | (g1 >> 8)) & rem;
                    if (g2 == cur) break;
                    cur = g2;
                }
                int a = __popcll(cur);
                if (a > best) best = a;
                rem ^= cur;
                nc++;
            }
        } else {
            ones = __popcll(mlo) + __popcll(mhi);
            best = KK - ones;
            u64 nlo, nhi;
            expand128<K>(mlo, mhi, nlo, nhi);
            u64 isolo = mlo & ~nlo, isohi = mhi & ~nhi;
            nc = __popcll(isolo) + __popcll(isohi);
            u64 rlo = mlo ^ isolo, rhi = mhi ^ isohi;
            while (rlo | rhi) {
                u64 clo, chi;
                if (rlo) { clo = rlo & (0ull - rlo); chi = 0; }
                else     { clo = 0; chi = rhi & (0ull - rhi); }
                while (true) {
                    u64 elo, ehi, g1lo, g1hi, g2lo, g2hi;
                    expand128<K>(clo, chi, elo, ehi);
                    g1lo = (clo | elo) & rlo;
                    g1hi = (chi | ehi) & rhi;
                    expand128<K>(g1lo, g1hi, elo, ehi);
                    g2lo = (g1lo | elo) & rlo;
                    g2hi = (g1hi | ehi) & rhi;
                    if (g2lo == clo && g2hi == chi) break;
                    clo = g2lo; chi = g2hi;
                }
                int a = __popcll(clo) + __popcll(chi);
                if (a > best) best = a;
                rlo ^= clo; rhi ^= chi;
                nc++;
            }
        }

        // Warp-aggregated histogram add: one atomic per distinct bin per warp
        {
            unsigned act   = __activemask();
            unsigned peers = __match_any_sync(act, ones);
            int lane = threadIdx.x & 31;
            if (lane == (__ffs(peers) - 1))
                atomicAdd(&sh[ones], __popc(peers));
        }
        t_nc += nc;
        t_pc += (ones >= PTH) ? 1 : 0;
        t_ma += best;
    }

    atomicAdd(&sh[128], t_nc);
    atomicAdd(&sh[129], t_pc);
    atomicAdd(&sh[130], t_ma);
    __syncthreads();

    int* dst = g_acc + (SEG * NPAIR + pair) * ACC_STRIDE;
    for (int i = threadIdx.x; i < ACC_STRIDE - 1; i += 256) {
        int v = sh[i];
        if (v) atomicAdd(&dst[i], v);
    }
}

__global__ __launch_bounds__(256) void patch_all_kernel() {
    __shared__ int sh[ACC_STRIDE - 1];
    const int blk = blockIdx.x;
    if (blk < O9)       patch_body<11, C11, 0>(blk - O11, sh);
    else if (blk < O7)  patch_body<9,  C9,  1>(blk - O9,  sh);
    else if (blk < O5)  patch_body<7,  C7,  2>(blk - O7,  sh);
    else if (blk < O3)  patch_body<5,  C5,  3>(blk - O5,  sh);
    else                patch_body<3,  C3,  4>(blk - O3,  sh);
}

// ---------------------------------------------------------------------------
// Kernel 3: finalize metrics -> (B,5,5,3) feature map (1 thread per seg,pair)
// ---------------------------------------------------------------------------
__global__ void finalize_kernel() {
    int tid = blockIdx.x * blockDim.x + threadIdx.x;
    if (tid >= 5 * NPAIR) return;
    const int seg  = tid / NPAIR;
    const int pair = tid % NPAIR;
    const int b  = pair / 3;
    const int ch = pair % 3;

    const int K  = 11 - 2 * seg;          // seg order: 11,9,7,5,3
    const int KK = K * K;
    const int ROWS = (H + K - 1) / K;
    const int COLS = (W + K - 1) / K;
    const int P    = ROWS * COLS;

    const int* acc = g_acc + (seg * NPAIR + pair) * ACC_STRIDE;
    const float fP = (float)P;
    float fd = 0.0f, m = 0.0f, m2 = 0.0f;
    for (int q = 0; q < KK; q++) {
        float p = (float)acc[q] / fP;
        float n = (float)(q + 1);
        fd += p / n;
        m  += p * n;
        m2 += p * p * n;
    }
    float lac = (m2 - m * m) / (m * m);
    int acn  = acc[128] / P;
    int acp  = acc[129] / P;
    int acma = acc[130] / P;

    const int kidx = (K - 3) / 2;
    const int o = ((b * 5) * 5 + kidx) * 3 + ch;
    g_feat[o + 0 * 15] = (float)acn;
    g_feat[o + 1 * 15] = (float)acp;
    g_feat[o + 2 * 15] = (float)acma;
    g_feat[o + 3 * 15] = lac;
    g_feat[o + 4 * 15] = fd;
}

// ---------------------------------------------------------------------------
// Kernel 4: bilinear resize via smem pre-lerped rows, float4 LDS
// ---------------------------------------------------------------------------
#define RCHUNK 28
#define YBLKS (H / RCHUNK)   // 8
#define WC (W * 3)           // 672

__global__ __launch_bounds__(256) void resize_kernel(float* __restrict__ out) {
    __shared__ float feat[75];
    __shared__ __align__(16) float hrow[5 * WC];   // 3360
    __shared__ float s_fy[RCHUNK];
    __shared__ int   s_y0[RCHUNK], s_y1[RCHUNK];

    const int b   = blockIdx.x / YBLKS;
    const int yc  = blockIdx.x % YBLKS;
    const int tid = threadIdx.x;

    if (tid < 75) feat[tid] = g_feat[b * 75 + tid];
    if (tid >= 96 && tid < 96 + RCHUNK) {
        int y = yc * RCHUNK + (tid - 96);
        float cy = ((float)y + 0.5f) * (5.0f / 224.0f) - 0.5f;
        float fl = floorf(cy);
        int y0 = (int)fl;
        float fy = cy - fl;
        int y0c = max(y0, 0), y1c = min(y0 + 1, 4);
        s_fy[tid - 96] = fy;
        s_y0[tid - 96] = y0c * WC;
        s_y1[tid - 96] = y1c * WC;
    }
    __syncthreads();

    for (int i = tid; i < 5 * WC; i += 256) {
        int r  = i / WC;
        int xc = i - r * WC;
        int x  = xc / 3;
        int ch = xc - x * 3;
        float cx = ((float)x + 0.5f) * (5.0f / 224.0f) - 0.5f;
        float fl = floorf(cx);
        int x0 = (int)fl;
        float fx = cx - fl;
        int x0c = max(x0, 0), x1c = min(x0 + 1, 4);
        float a  = feat[(r * 5 + x0c) * 3 + ch];
        float bb = feat[(r * 5 + x1c) * 3 + ch];
        hrow[i] = a + fx * (bb - a);
    }
    __syncthreads();

    float4* o4 = (float4*)(out + b * (H * WC) + yc * (RCHUNK * WC));
    const int N4 = RCHUNK * WC / 4;   // 4704
    for (int i = tid; i < N4; i += 256) {
        int yl = i / (WC / 4);
        int x4 = i - yl * (WC / 4);
        const float4 a  = *(const float4*)&hrow[s_y0[yl] + 4 * x4];
        const float4 bb = *(const float4*)&hrow[s_y1[yl] + 4 * x4];
        const float fy = s_fy[yl];
        float4 v;
        v.x = a.x + fy * (bb.x - a.x);
        v.y = a.y + fy * (bb.y - a.y);
        v.z = a.z + fy * (bb.z - a.z);
        v.w = a.w + fy * (bb.w - a.w);
        o4[i] = v;
    }
}

// ---------------------------------------------------------------------------
extern "C" void kernel_launch(void* const* d_in, const int* in_sizes, int n_in,
                              void* d_out, int out_size) {
    const float4* in4 = (const float4*)d_in[0];
    float* out = (float*)d_out;

    const int NT = BATCH * H * W / 4;   // 802816
    transpose_kernel<<<NT / 256, 256>>>(in4);
    patch_all_kernel<<<TOTAL_BLOCKS, 256>>>();
    finalize_kernel<<<(5 * NPAIR + 255) / 256, 256>>>();
    resize_kernel<<<BATCH * YBLKS, 256>>>(out);
}